// round 5
// baseline (speedup 1.0000x reference)
#include <cuda_runtime.h>

// Output == input (reference returns x reshaped; all other computation is dead).
// Pure copy at the DRAM r+w ceiling. Probe: 256-bit LDG/STG (sm_100+) for
// longer DRAM bursts / fewer L1tex wavefronts.
//
// n floats = 75,497,472 ; as 32B chunks: 9,437,184 = 9216 * 256 * 4 exactly.

struct __align__(32) f8 { float4 a, b; };

__device__ __forceinline__ f8 ldg256_cs(const f8* p) {
    f8 v;
    asm volatile("ld.global.cs.v8.f32 {%0,%1,%2,%3,%4,%5,%6,%7}, [%8];"
                 : "=f"(v.a.x), "=f"(v.a.y), "=f"(v.a.z), "=f"(v.a.w),
                   "=f"(v.b.x), "=f"(v.b.y), "=f"(v.b.z), "=f"(v.b.w)
                 : "l"(p));
    return v;
}

__device__ __forceinline__ void stg256_cs(f8* p, const f8& v) {
    asm volatile("st.global.cs.v8.f32 [%0], {%1,%2,%3,%4,%5,%6,%7,%8};"
                 :: "l"(p),
                    "f"(v.a.x), "f"(v.a.y), "f"(v.a.z), "f"(v.a.w),
                    "f"(v.b.x), "f"(v.b.y), "f"(v.b.z), "f"(v.b.w)
                 : "memory");
}

__global__ void __launch_bounds__(256) copy256_kernel(const f8* __restrict__ src,
                                                      f8* __restrict__ dst) {
    unsigned i = blockIdx.x * 1024u + threadIdx.x;  // 1024 = 256 threads * 4 chunks
    f8 v0 = ldg256_cs(src + i);
    f8 v1 = ldg256_cs(src + i + 256u);
    f8 v2 = ldg256_cs(src + i + 512u);
    f8 v3 = ldg256_cs(src + i + 768u);
    stg256_cs(dst + i,         v0);
    stg256_cs(dst + i + 256u,  v1);
    stg256_cs(dst + i + 512u,  v2);
    stg256_cs(dst + i + 768u,  v3);
}

// Generic fallback for unexpected sizes.
__global__ void copy_generic(const float* __restrict__ src, float* __restrict__ dst,
                             long long n) {
    long long i = (long long)blockIdx.x * blockDim.x + threadIdx.x;
    long long stride = (long long)gridDim.x * blockDim.x;
    for (; i < n; i += stride) dst[i] = src[i];
}

extern "C" void kernel_launch(void* const* d_in, const int* in_sizes, int n_in,
                              void* d_out, int out_size) {
    (void)n_in;
    long long n = out_size;
    if (n == 75497472LL && in_sizes[0] >= out_size) {
        copy256_kernel<<<9216, 256>>>((const f8*)d_in[0], (f8*)d_out);
    } else {
        long long nn = n;
        if ((long long)in_sizes[0] < nn) nn = in_sizes[0];
        int blocks = (int)((nn + 255) / 256);
        if (blocks > 147456) blocks = 147456;
        copy_generic<<<blocks, 256>>>((const float*)d_in[0], (float*)d_out, nn);
    }
}